// round 11
// baseline (speedup 1.0000x reference)
#include <cuda_runtime.h>
#include <cuda_fp16.h>
#include <cstdint>

#define N_ROWS 4096
#define DIM    768
#define HID    16384

// GEMM tiling (BM=256 x BN=128, 512 threads, warp tile 64x32)
#define BM 256
#define BN 128
#define BK 32
#define NKT (DIM / BK)          // 24
#define PITCH_H 40              // halves per smem row (80B, LDSM conflict-free)
#define A_BYTES (256 * PITCH_H * 2)     // 20480
#define B_BYTES (128 * PITCH_H * 2)     // 10240
#define STAGE_BYTES (A_BYTES + B_BYTES) // 30720
#define SMEM_GEMM (3 * STAGE_BYTES)     // 92160 (3-stage)

#define REFINE_SMEM (3072 + 16 * 772 * 4)   // es[768] + ws[16][772]
#define SELECT_SMEM 32768                   // 8192 packed key words

// ---------------- scratch (static device globals; no allocation) ----------------
__device__ __half g_cosh[(size_t)N_ROWS * HID];    // 128 MB approx cos
__device__ float  g_WT[(size_t)HID * DIM];         // 48 MB
__device__ float  g_invE[N_ROWS];
__device__ float  g_invW[HID];
__device__ __half g_Enh[(size_t)N_ROWS * DIM];     // normalized f16
__device__ __half g_Wnh[(size_t)HID * DIM];        // normalized f16
__device__ int    g_cand[N_ROWS * 64];
__device__ int    g_ccnt[N_ROWS];
__device__ int    g_aidx[N_ROWS * 64];
__device__ float  g_aval[N_ROWS * 64];
__device__ int    g_acnt[N_ROWS];

extern __shared__ __align__(1024) char dynsmem[];

// ---------------- PTX helpers (base-target ISA only) ----------------
__device__ __forceinline__ uint32_t smem_u32(const void* p) {
    uint32_t a;
    asm("{ .reg .u64 t; cvta.to.shared.u64 t, %1; cvt.u32.u64 %0, t; }" : "=r"(a) : "l"(p));
    return a;
}
__device__ __forceinline__ void cp16(uint32_t dst, const void* src) {
    asm volatile("cp.async.cg.shared.global [%0], [%1], 16;" :: "r"(dst), "l"(src));
}
__device__ __forceinline__ void cp_commit() { asm volatile("cp.async.commit_group;"); }
__device__ __forceinline__ void cp_wait1()  { asm volatile("cp.async.wait_group 1;"); }
__device__ __forceinline__ void ldsm_x4(uint32_t* r, uint32_t addr) {
    asm volatile("ldmatrix.sync.aligned.m8n8.x4.shared.b16 {%0,%1,%2,%3}, [%4];"
                 : "=r"(r[0]), "=r"(r[1]), "=r"(r[2]), "=r"(r[3]) : "r"(addr));
}
__device__ __forceinline__ void mma16816(float* c, const uint32_t* a, uint32_t b0, uint32_t b1) {
    asm volatile(
        "mma.sync.aligned.m16n8k16.row.col.f32.f16.f16.f32 "
        "{%0,%1,%2,%3}, {%4,%5,%6,%7}, {%8,%9}, {%0,%1,%2,%3};"
        : "+f"(c[0]), "+f"(c[1]), "+f"(c[2]), "+f"(c[3])
        : "r"(a[0]), "r"(a[1]), "r"(a[2]), "r"(a[3]), "r"(b0), "r"(b1));
}

// ---------------- fused: EXACT round-1 inverse norm + normalized f16 copy ----------------
__global__ void normhalf_kernel(const float* __restrict__ X, float* __restrict__ inv,
                                __half* __restrict__ Xh, int rows)
{
    int row = blockIdx.x * 8 + threadIdx.y;
    if (row >= rows) return;
    const float* p = X + (size_t)row * DIM;
    float v[24];
    float s = 0.f;
    #pragma unroll
    for (int q = 0; q < 24; q++) {
        v[q] = p[threadIdx.x + q * 32];
        s = fmaf(v[q], v[q], s);
    }
    #pragma unroll
    for (int o = 16; o > 0; o >>= 1) s += __shfl_xor_sync(0xffffffffu, s, o);
    float iv = 1.0f / fmaxf(sqrtf(s), 1e-12f);
    if (threadIdx.x == 0) inv[row] = iv;
    __half* hp = Xh + (size_t)row * DIM;
    #pragma unroll
    for (int q = 0; q < 24; q++)
        hp[threadIdx.x + q * 32] = __float2half_rn(v[q] * iv);
}

// ---------------- HMMA f16 GEMM: cos_h[4096,16384] = En . WnT (approx) ----------------
// BM=256 halves B global traffic vs R10 (cp.async-issue bound). Per-output k-order
// identical to R10 -> bitwise-identical cos_h.
__global__ void __launch_bounds__(512, 1) cos_gemm_kernel(
    const __half* __restrict__ Ah, const __half* __restrict__ Bh,
    __half* __restrict__ C)
{
    char* smem = dynsmem;
    const uint32_t sb = smem_u32(smem);
    const int tid = threadIdx.x, wid = tid >> 5, lane = tid & 31;
    const int warp_m = wid >> 2, warp_n = wid & 3;   // 4 x 4 warps (64x32 tiles)
    const int bn = blockIdx.x, bm = blockIdx.y;

    const __half* Abase = Ah + (size_t)bm * BM * DIM;
    const __half* Bbase = Bh + (size_t)bn * BN * DIM;

    // cp.async coords: A has 1024 16B-chunks (256 rows x 4), B has 512 (128 rows x 4).
    const int ra0 = tid >> 2, ca = tid & 3;          // A chunk tid     (rows 0..127)
    const int ra1 = (tid + 512) >> 2;                // A chunk tid+512 (rows 128..255)
    const int rb  = tid >> 2;                        // B chunk tid (tid<512 all valid rows 0..127)

    const int a_tile = lane >> 3, a_r = lane & 7;
    const uint32_t a_off = (uint32_t)((warp_m * 64 + (a_tile & 1) * 8 + a_r) * (PITCH_H * 2)
                                      + ((a_tile >> 1) * 8) * 2);
    const uint32_t b_off = (uint32_t)((warp_n * 32 + (a_tile >> 1) * 8 + a_r) * (PITCH_H * 2)
                                      + ((a_tile & 1) * 8) * 2);

    float acc[4][4][4];
    #pragma unroll
    for (int i = 0; i < 4; i++)
        #pragma unroll
        for (int j = 0; j < 4; j++)
            #pragma unroll
            for (int q = 0; q < 4; q++) acc[i][j][q] = 0.f;

    auto issue = [&](int s) {
        if (s < NKT) {
            const int kb = s * BK;
            const uint32_t stg = sb + (uint32_t)(s % 3) * STAGE_BYTES;
            cp16(stg + ra0 * (PITCH_H * 2) + ca * 16, Abase + (size_t)ra0 * DIM + kb + ca * 8);
            cp16(stg + ra1 * (PITCH_H * 2) + ca * 16, Abase + (size_t)ra1 * DIM + kb + ca * 8);
            cp16(stg + A_BYTES + rb * (PITCH_H * 2) + ca * 16, Bbase + (size_t)rb * DIM + kb + ca * 8);
        }
        cp_commit();
    };

    issue(0);
    issue(1);

    for (int kt = 0; kt < NKT; ++kt) {
        cp_wait1();
        __syncthreads();
        issue(kt + 2);
        const uint32_t stg = sb + (uint32_t)(kt % 3) * STAGE_BYTES;
        #pragma unroll
        for (int ks = 0; ks < 2; ++ks) {
            const uint32_t kadd = (uint32_t)(ks * 16 * 2);
            uint32_t AH[16], BH[8];
            #pragma unroll
            for (int mt = 0; mt < 4; mt++)
                ldsm_x4(&AH[mt * 4], stg + a_off + mt * 16 * (PITCH_H * 2) + kadd);
            #pragma unroll
            for (int np = 0; np < 2; np++)
                ldsm_x4(&BH[np * 4], stg + A_BYTES + b_off + np * 16 * (PITCH_H * 2) + kadd);
            #pragma unroll
            for (int mt = 0; mt < 4; mt++)
                #pragma unroll
                for (int nt = 0; nt < 4; nt++)
                    mma16816(acc[mt][nt], &AH[mt * 4], BH[nt * 2], BH[nt * 2 + 1]);
        }
    }

    const int m0 = bm * BM + warp_m * 64 + (lane >> 2);
    const int n0 = bn * BN + warp_n * 32 + (lane & 3) * 2;
    #pragma unroll
    for (int mt = 0; mt < 4; mt++)
        #pragma unroll
        for (int nt = 0; nt < 4; nt++) {
            __half* p0 = C + (size_t)(m0 + mt * 16) * HID + n0 + nt * 8;
            __half* p1 = C + (size_t)(m0 + mt * 16 + 8) * HID + n0 + nt * 8;
            *(__half2*)p0 = __floats2half2_rn(acc[mt][nt][0], acc[mt][nt][1]);
            *(__half2*)p1 = __floats2half2_rn(acc[mt][nt][2], acc[mt][nt][3]);
        }
}

// ---------------- candidate select: smem-key, bounded 2-phase windowed radix ----------------
__device__ __forceinline__ void scan_hist(const unsigned* hist, int T, int lane,
                                          int* sh_cross, int* sh_rem, int* sh_total)
{
    unsigned h8[8];
    int s = 0;
    #pragma unroll
    for (int j = 0; j < 8; j++) { h8[j] = hist[lane * 8 + j]; s += (int)h8[j]; }
    int t = s;
    #pragma unroll
    for (int o = 1; o < 32; o <<= 1) {
        int v = __shfl_down_sync(0xffffffffu, t, o);
        if (lane + o < 32) t += v;
    }
    int above = __shfl_down_sync(0xffffffffu, t, 1);
    if (lane == 31) above = 0;
    const int total = __shfl_sync(0xffffffffu, t, 0);
    int cum = above;
    #pragma unroll
    for (int j = 7; j >= 0; j--) {
        if (cum < T && cum + (int)h8[j] >= T) {
            *sh_cross = lane * 8 + j;
            *sh_rem = T - cum;
        }
        cum += (int)h8[j];
    }
    if (lane == 0) *sh_total = total;
}

__global__ void __launch_bounds__(256) select_kernel(
    const __half* __restrict__ S, int* __restrict__ cand, int* __restrict__ ccnt,
    const int* __restrict__ topk_ptr)
{
    uint32_t* kp = (uint32_t*)dynsmem;      // 8192 packed key16 pairs (32 KB)
    __shared__ unsigned hist[256];
    __shared__ unsigned wmax[8];
    __shared__ int sh_cross, sh_rem, sh_total, sh_cnt, sh_lb;

    const int n = blockIdx.x, tid = threadIdx.x;
    const int wid = tid >> 5, lane = tid & 31;
    const int T = *topk_ptr + 8;

    const uint4* g4 = (const uint4*)(S + (size_t)n * HID);
    uint32_t mymax = 0;
    #pragma unroll
    for (int i = 0; i < 8; i++) {
        const int w4 = tid + i * 256;
        uint4 v = g4[w4];
        uint32_t wsv[4] = {v.x, v.y, v.z, v.w};
        #pragma unroll
        for (int c = 0; c < 4; c++) {
            uint32_t w = wsv[c];
            uint32_t m = (w >> 15) & 0x00010001u;
            uint32_t key = w ^ ((m * 0xFFFFu) | 0x80008000u);
            kp[w4 * 4 + c] = key;
            mymax = max(mymax, max(key & 0xFFFF0000u, key << 16));
        }
    }
    mymax >>= 16;
    #pragma unroll
    for (int o = 16; o > 0; o >>= 1)
        mymax = max(mymax, __shfl_xor_sync(0xffffffffu, mymax, o));
    if (lane == 0) wmax[wid] = mymax;
    if (tid == 0) { sh_cnt = 0; sh_cross = 255; sh_rem = T; sh_lb = 255; sh_total = 0; }
    hist[tid] = 0u;
    __syncthreads();
    uint32_t maxkey = 0;
    #pragma unroll
    for (int j = 0; j < 8; j++) maxkey = max(maxkey, wmax[j]);
    int floorA = (int)(maxkey >> 8) - 4;
    if (floorA < 0) floorA = 0;

    // phase A: histogram high bytes in [floorA, 256)
    #pragma unroll
    for (int i = 0; i < 32; i++) {
        const uint32_t key = kp[tid + i * 256];
        #pragma unroll
        for (int h = 0; h < 2; h++) {
            const int hb = (int)((key >> (8 + 16 * h)) & 0xFFu);
            const bool pass = (hb >= floorA);
            const unsigned act = __ballot_sync(0xffffffffu, pass);
            if (!act) continue;
            const unsigned d = pass ? (unsigned)hb : 0xFFFFFFFFu;
            const unsigned grp = __match_any_sync(0xffffffffu, d);
            if (pass && lane == __ffs(grp) - 1)
                atomicAdd(&hist[hb], (unsigned)__popc(grp));
        }
    }
    __syncthreads();
    if (wid == 0) scan_hist(hist, T, lane, &sh_cross, &sh_rem, &sh_total);
    __syncthreads();

    // phase B (at most once): full coverage after.
    if (sh_total < T && floorA > 0) {
        #pragma unroll
        for (int i = 0; i < 32; i++) {
            const uint32_t key = kp[tid + i * 256];
            #pragma unroll
            for (int h = 0; h < 2; h++) {
                const int hb = (int)((key >> (8 + 16 * h)) & 0xFFu);
                const bool pass = (hb < floorA);
                const unsigned act = __ballot_sync(0xffffffffu, pass);
                if (!act) continue;
                const unsigned d = pass ? (unsigned)hb : 0xFFFFFFFFu;
                const unsigned grp = __match_any_sync(0xffffffffu, d);
                if (pass && lane == __ffs(grp) - 1)
                    atomicAdd(&hist[hb], (unsigned)__popc(grp));
            }
        }
        __syncthreads();
        if (wid == 0) scan_hist(hist, T, lane, &sh_cross, &sh_rem, &sh_total);
        __syncthreads();
    }
    const int cross = sh_cross, rem = sh_rem;
    __syncthreads();
    hist[tid] = 0u;
    __syncthreads();

    // low-byte histogram within crossing bin
    #pragma unroll
    for (int i = 0; i < 32; i++) {
        const uint32_t key = kp[tid + i * 256];
        #pragma unroll
        for (int h = 0; h < 2; h++) {
            const unsigned k = (key >> (16 * h)) & 0xFFFFu;
            const bool pass = ((int)(k >> 8) == cross);
            const unsigned act = __ballot_sync(0xffffffffu, pass);
            if (!act) continue;
            const unsigned d = pass ? (k & 0xFFu) : 0xFFFFFFFFu;
            const unsigned grp = __match_any_sync(0xffffffffu, d);
            if (pass && lane == __ffs(grp) - 1)
                atomicAdd(&hist[k & 0xFFu], (unsigned)__popc(grp));
        }
    }
    __syncthreads();
    if (wid == 0) scan_hist(hist, rem, lane, &sh_lb, &sh_rem, &sh_total);
    __syncthreads();
    const unsigned Kcut = ((unsigned)cross << 8) | (unsigned)sh_lb;

    // gather candidates (warp-aggregated append; shuffle executed by ALL lanes)
    #pragma unroll
    for (int i = 0; i < 32; i++) {
        const int w = tid + i * 256;
        const uint32_t key = kp[w];
        #pragma unroll
        for (int h = 0; h < 2; h++) {
            const unsigned k = (key >> (16 * h)) & 0xFFFFu;
            const bool pass = (k >= Kcut);
            const unsigned grp = __ballot_sync(0xffffffffu, pass);
            if (!grp) continue;
            const int leader = __ffs(grp) - 1;
            int base = 0;
            if (lane == leader) base = atomicAdd(&sh_cnt, __popc(grp));
            base = __shfl_sync(0xffffffffu, base, leader);
            if (pass) {
                const int pos = base + __popc(grp & ((1u << lane) - 1u));
                if (pos < 64)
                    cand[n * 64 + pos] = w * 2 + h;
            }
        }
    }
    __syncthreads();
    if (tid == 0) ccnt[n] = min(sh_cnt, 64);
}

// ---------------- refine: EXACT round-1 arithmetic on candidates ----------------
__global__ void __launch_bounds__(256) refine_kernel(
    const float* __restrict__ Eraw, const float* __restrict__ Wraw,
    const float* __restrict__ invE, const float* __restrict__ invW,
    const int* __restrict__ cand, const int* __restrict__ ccnt,
    float* __restrict__ latent, int* __restrict__ acnt,
    int* __restrict__ aidx, float* __restrict__ aval,
    const int* __restrict__ topk_ptr)
{
    float* es = (float*)dynsmem;          // 768 floats (raw E row)
    float* ws = es + 768;                 // 16 rows x 772 floats (raw W rows)
    __shared__ float simc[64];
    __shared__ int   ridx[64];
    __shared__ int   skeep[64];
    __shared__ float sh_thres;

    const int n = blockIdx.x, tid = threadIdx.x;
    const int cnt = min(ccnt[n], 64);
    const int K = *topk_ptr;
    const float ie = invE[n];

    if (tid == 0) sh_thres = -1e30f;
    if (tid < 192) ((float4*)es)[tid] = ((const float4*)(Eraw + (size_t)n * DIM))[tid];
    __syncthreads();

    for (int base = 0; base < cnt; base += 16) {
        const int nthis = min(16, cnt - base);
        const int r = tid >> 4, part = tid & 15;
        if (r < nthis) {
            const float4* wr = (const float4*)(Wraw + (size_t)cand[n * 64 + base + r] * DIM);
            float4* wd = (float4*)(ws + r * 772);
            #pragma unroll
            for (int j = 0; j < 12; j++) wd[part + j * 16] = wr[part + j * 16];
        }
        __syncthreads();
        if (tid < nthis) {
            const int id = cand[n * 64 + base + tid];
            const float* wrow = ws + tid * 772;
            float s = 0.f;
            for (int k = 0; k < DIM; k++) s = fmaf(es[k], wrow[k], s);
            float cosv = s * ie * invW[id];
            float t = fmaxf(2.0f - 2.0f * cosv, 0.0f);
            simc[base + tid] = 2.0f - sqrtf(t);
            ridx[base + tid] = id;
        }
        __syncthreads();
    }

    if (tid < cnt) {
        float x = simc[tid];
        int id = ridx[tid];
        int r = 0;
        for (int j = 0; j < cnt; j++)
            r += (simc[j] > x) || (simc[j] == x && ridx[j] < id);
        if (r == K) sh_thres = x;
    }
    __syncthreads();
    const float thres = sh_thres;
    if (tid < 64) skeep[tid] = (tid < cnt) ? (simc[tid] > thres ? 1 : 0) : 0;
    __syncthreads();
    if (tid < cnt && skeep[tid]) {
        float sim = simc[tid];
        latent[(size_t)n * HID + ridx[tid]] = sim;
        int pos = 0;
        for (int j = 0; j < cnt; j++)
            pos += (skeep[j] && ridx[j] < ridx[tid]) ? 1 : 0;
        aidx[n * 64 + pos] = ridx[tid];
        aval[n * 64 + pos] = sim;
    }
    if (tid == 0) {
        int tot = 0;
        for (int j = 0; j < cnt; j++) tot += skeep[j];
        acnt[n] = tot;
    }
}

// ---------------- transpose W [DIM][HID] -> WT [HID][DIM] ----------------
__global__ void transpose_kernel(const float* __restrict__ Win, float* __restrict__ Wout)
{
    __shared__ float t[32][33];
    const int h0 = blockIdx.x * 32, d0 = blockIdx.y * 32;
    const int x = threadIdx.x, y = threadIdx.y;
    #pragma unroll
    for (int i = y; i < 32; i += 8)
        t[i][x] = Win[(size_t)(d0 + i) * HID + h0 + x];
    __syncthreads();
    #pragma unroll
    for (int i = y; i < 32; i += 8)
        Wout[(size_t)(h0 + i) * DIM + d0 + x] = t[x][i];
}

// ---------------- sparse reconstruction ----------------
__global__ void __launch_bounds__(256) recon_kernel(
    const float* __restrict__ WT, const float* __restrict__ bias,
    float* __restrict__ R, const int* __restrict__ acnt,
    const int* __restrict__ aidx, const float* __restrict__ aval)
{
    const int n = blockIdx.x, tid = threadIdx.x;
    __shared__ int   sidx[64];
    __shared__ float sval[64];
    int c = acnt[n];
    if (c > 64) c = 64;
    if (tid < 64) {
        sidx[tid] = aidx[n * 64 + tid];
        sval[tid] = aval[n * 64 + tid];
    }
    __syncthreads();
    float a0 = bias[tid], a1 = bias[tid + 256], a2 = bias[tid + 512];
    for (int j = 0; j < c; j++) {
        const float* w = WT + (size_t)sidx[j] * DIM;
        const float v = sval[j];
        a0 = fmaf(v, w[tid],       a0);
        a1 = fmaf(v, w[tid + 256], a1);
        a2 = fmaf(v, w[tid + 512], a2);
    }
    float* r = R + (size_t)n * DIM;
    r[tid] = a0; r[tid + 256] = a1; r[tid + 512] = a2;
}

// ---------------- host ----------------
extern "C" void kernel_launch(void* const* d_in, const int* in_sizes, int n_in,
                              void* d_out, int out_size)
{
    const float* Ev  = (const float*)d_in[0];
    const float* Et  = (const float*)d_in[1];
    const float* Enc = (const float*)d_in[2];
    const float* Wv  = (const float*)d_in[3];
    const float* bv  = (const float*)d_in[4];
    const float* Wt  = (const float*)d_in[5];
    const float* bt  = (const float*)d_in[6];
    const int*   tk  = (const int*)d_in[7];

    float* out = (float*)d_out;
    float* recon_v  = out;
    float* recon_t  = out + (size_t)N_ROWS * DIM;
    float* latent_v = out + (size_t)2 * N_ROWS * DIM;
    float* latent_t = latent_v + (size_t)N_ROWS * HID;

    __half *p_cosh, *p_Enh, *p_Wnh;
    float *p_WT, *p_invE, *p_invW, *p_aval;
    int *p_cand, *p_ccnt, *p_aidx, *p_acnt;
    cudaGetSymbolAddress((void**)&p_cosh, g_cosh);
    cudaGetSymbolAddress((void**)&p_WT,   g_WT);
    cudaGetSymbolAddress((void**)&p_invE, g_invE);
    cudaGetSymbolAddress((void**)&p_invW, g_invW);
    cudaGetSymbolAddress((void**)&p_Enh,  g_Enh);
    cudaGetSymbolAddress((void**)&p_Wnh,  g_Wnh);
    cudaGetSymbolAddress((void**)&p_cand, g_cand);
    cudaGetSymbolAddress((void**)&p_ccnt, g_ccnt);
    cudaGetSymbolAddress((void**)&p_aidx, g_aidx);
    cudaGetSymbolAddress((void**)&p_aval, g_aval);
    cudaGetSymbolAddress((void**)&p_acnt, g_acnt);

    cudaFuncSetAttribute(cos_gemm_kernel, cudaFuncAttributeMaxDynamicSharedMemorySize, SMEM_GEMM);
    cudaFuncSetAttribute(select_kernel,   cudaFuncAttributeMaxDynamicSharedMemorySize, SELECT_SMEM);
    cudaFuncSetAttribute(refine_kernel,   cudaFuncAttributeMaxDynamicSharedMemorySize, REFINE_SMEM);

    const dim3 tb(32, 8);
    const dim3 ggrid(HID / BN, N_ROWS / BM);   // (128, 16)

    normhalf_kernel<<<HID / 8, tb>>>(Enc, p_invW, p_Wnh, HID);

    // ---- vision ----
    normhalf_kernel<<<N_ROWS / 8, tb>>>(Ev, p_invE, p_Enh, N_ROWS);
    cos_gemm_kernel<<<ggrid, 512, SMEM_GEMM>>>(p_Enh, p_Wnh, p_cosh);
    select_kernel<<<N_ROWS, 256, SELECT_SMEM>>>(p_cosh, p_cand, p_ccnt, tk);
    cudaMemsetAsync(latent_v, 0, (size_t)2 * N_ROWS * HID * sizeof(float));
    refine_kernel<<<N_ROWS, 256, REFINE_SMEM>>>(Ev, Enc, p_invE, p_invW, p_cand, p_ccnt,
                                                latent_v, p_acnt, p_aidx, p_aval, tk);
    transpose_kernel<<<dim3(HID / 32, DIM / 32), tb>>>(Wv, p_WT);
    recon_kernel<<<N_ROWS, 256>>>(p_WT, bv, recon_v, p_acnt, p_aidx, p_aval);

    // ---- text ----
    normhalf_kernel<<<N_ROWS / 8, tb>>>(Et, p_invE, p_Enh, N_ROWS);
    cos_gemm_kernel<<<ggrid, 512, SMEM_GEMM>>>(p_Enh, p_Wnh, p_cosh);
    select_kernel<<<N_ROWS, 256, SELECT_SMEM>>>(p_cosh, p_cand, p_ccnt, tk);
    refine_kernel<<<N_ROWS, 256, REFINE_SMEM>>>(Et, Enc, p_invE, p_invW, p_cand, p_ccnt,
                                                latent_t, p_acnt, p_aidx, p_aval, tk);
    transpose_kernel<<<dim3(HID / 32, DIM / 32), tb>>>(Wt, p_WT);
    recon_kernel<<<N_ROWS, 256>>>(p_WT, bt, recon_t, p_acnt, p_aidx, p_aval);
}

// round 12
// speedup vs baseline: 1.1096x; 1.1096x over previous
#include <cuda_runtime.h>
#include <cuda_fp16.h>
#include <cstdint>

#define N_ROWS 4096
#define DIM    768
#define HID    16384

// GEMM tiling (R10 config: BM=128 x BN=128, 256 threads, 2 CTAs/SM)
#define BM 128
#define BN 128
#define BK 32
#define NKT (DIM / BK)          // 24
#define PITCH_H 40              // halves per smem row (80B, LDSM conflict-free)
#define ARR_BYTES (128 * PITCH_H * 2)   // 10240 B per array (128 rows x BK)
#define STAGE_BYTES (2 * ARR_BYTES)     // A | B = 20480
#define SMEM_GEMM (3 * STAGE_BYTES)     // 61440 (3-stage)

#define REFINE_SMEM (3072 + 16 * 772 * 4)   // es[768] + ws[16][772]
#define SELECT_SMEM 32768                   // 8192 packed key words

// ---------------- scratch (static device globals; no allocation) ----------------
__device__ __half g_cosh[(size_t)N_ROWS * HID];    // 128 MB approx cos
__device__ float  g_WT[(size_t)HID * DIM];         // 48 MB
__device__ float  g_invE[N_ROWS];
__device__ float  g_invW[HID];
__device__ __half g_Enh[(size_t)N_ROWS * DIM];     // normalized f16
__device__ __half g_Wnh[(size_t)HID * DIM];        // normalized f16
__device__ int    g_cand[N_ROWS * 64];
__device__ int    g_ccnt[N_ROWS];
__device__ int    g_aidx[N_ROWS * 64];
__device__ float  g_aval[N_ROWS * 64];
__device__ int    g_acnt[N_ROWS];

extern __shared__ __align__(1024) char dynsmem[];

// ---------------- PTX helpers (base-target ISA only) ----------------
__device__ __forceinline__ uint32_t smem_u32(const void* p) {
    uint32_t a;
    asm("{ .reg .u64 t; cvta.to.shared.u64 t, %1; cvt.u32.u64 %0, t; }" : "=r"(a) : "l"(p));
    return a;
}
__device__ __forceinline__ void cp16(uint32_t dst, const void* src) {
    asm volatile("cp.async.cg.shared.global [%0], [%1], 16;" :: "r"(dst), "l"(src));
}
__device__ __forceinline__ void cp_commit() { asm volatile("cp.async.commit_group;"); }
__device__ __forceinline__ void cp_wait1()  { asm volatile("cp.async.wait_group 1;"); }
__device__ __forceinline__ void ldsm_x4(uint32_t* r, uint32_t addr) {
    asm volatile("ldmatrix.sync.aligned.m8n8.x4.shared.b16 {%0,%1,%2,%3}, [%4];"
                 : "=r"(r[0]), "=r"(r[1]), "=r"(r[2]), "=r"(r[3]) : "r"(addr));
}
__device__ __forceinline__ void mma16816(float* c, const uint32_t* a, uint32_t b0, uint32_t b1) {
    asm volatile(
        "mma.sync.aligned.m16n8k16.row.col.f32.f16.f16.f32 "
        "{%0,%1,%2,%3}, {%4,%5,%6,%7}, {%8,%9}, {%0,%1,%2,%3};"
        : "+f"(c[0]), "+f"(c[1]), "+f"(c[2]), "+f"(c[3])
        : "r"(a[0]), "r"(a[1]), "r"(a[2]), "r"(a[3]), "r"(b0), "r"(b1));
}

// ---------------- fused: EXACT round-1 inverse norm + normalized f16 copy ----------------
__global__ void normhalf_kernel(const float* __restrict__ X, float* __restrict__ inv,
                                __half* __restrict__ Xh, int rows)
{
    int row = blockIdx.x * 8 + threadIdx.y;
    if (row >= rows) return;
    const float* p = X + (size_t)row * DIM;
    float v[24];
    float s = 0.f;
    #pragma unroll
    for (int q = 0; q < 24; q++) {
        v[q] = p[threadIdx.x + q * 32];
        s = fmaf(v[q], v[q], s);
    }
    #pragma unroll
    for (int o = 16; o > 0; o >>= 1) s += __shfl_xor_sync(0xffffffffu, s, o);
    float iv = 1.0f / fmaxf(sqrtf(s), 1e-12f);
    if (threadIdx.x == 0) inv[row] = iv;
    __half* hp = Xh + (size_t)row * DIM;
    #pragma unroll
    for (int q = 0; q < 24; q++)
        hp[threadIdx.x + q * 32] = __float2half_rn(v[q] * iv);
}

// ---------------- HMMA f16 GEMM (R10 config): cos_h = En . WnT ----------------
__global__ void __launch_bounds__(256, 2) cos_gemm_kernel(
    const __half* __restrict__ Ah, const __half* __restrict__ Bh,
    __half* __restrict__ C)
{
    char* smem = dynsmem;
    const uint32_t sb = smem_u32(smem);
    const int tid = threadIdx.x, wid = tid >> 5, lane = tid & 31;
    const int warp_m = wid >> 2, warp_n = wid & 3;   // 2 x 4 warps
    const int bn = blockIdx.x, bm = blockIdx.y;

    const __half* gsrc[2] = {Ah + (size_t)bm * BM * DIM, Bh + (size_t)bn * BN * DIM};

    const int r0c = tid >> 2, c0c = tid & 3;
    const int r1c = (tid + 256) >> 2;

    const int a_tile = lane >> 3, a_r = lane & 7;
    const uint32_t a_off = (uint32_t)((warp_m * 64 + (a_tile & 1) * 8 + a_r) * (PITCH_H * 2)
                                      + ((a_tile >> 1) * 8) * 2);
    const uint32_t b_off = (uint32_t)((warp_n * 32 + (a_tile >> 1) * 8 + a_r) * (PITCH_H * 2)
                                      + ((a_tile & 1) * 8) * 2);

    float acc[4][4][4];
    #pragma unroll
    for (int i = 0; i < 4; i++)
        #pragma unroll
        for (int j = 0; j < 4; j++)
            #pragma unroll
            for (int q = 0; q < 4; q++) acc[i][j][q] = 0.f;

    auto issue = [&](int s) {
        if (s < NKT) {
            const int kb = s * BK;
            const uint32_t stg = sb + (uint32_t)(s % 3) * STAGE_BYTES;
            #pragma unroll
            for (int arr = 0; arr < 2; arr++) {
                const uint32_t sa = stg + arr * ARR_BYTES;
                cp16(sa + r0c * (PITCH_H * 2) + c0c * 16, gsrc[arr] + (size_t)r0c * DIM + kb + c0c * 8);
                cp16(sa + r1c * (PITCH_H * 2) + c0c * 16, gsrc[arr] + (size_t)r1c * DIM + kb + c0c * 8);
            }
        }
        cp_commit();
    };

    issue(0);
    issue(1);

    for (int kt = 0; kt < NKT; ++kt) {
        cp_wait1();
        __syncthreads();
        issue(kt + 2);
        const uint32_t stg = sb + (uint32_t)(kt % 3) * STAGE_BYTES;
        #pragma unroll
        for (int ks = 0; ks < 2; ++ks) {
            const uint32_t kadd = (uint32_t)(ks * 16 * 2);
            uint32_t AH[16], BH[8];
            #pragma unroll
            for (int mt = 0; mt < 4; mt++)
                ldsm_x4(&AH[mt * 4], stg + a_off + mt * 16 * (PITCH_H * 2) + kadd);
            #pragma unroll
            for (int np = 0; np < 2; np++)
                ldsm_x4(&BH[np * 4], stg + ARR_BYTES + b_off + np * 16 * (PITCH_H * 2) + kadd);
            #pragma unroll
            for (int mt = 0; mt < 4; mt++)
                #pragma unroll
                for (int nt = 0; nt < 4; nt++)
                    mma16816(acc[mt][nt], &AH[mt * 4], BH[nt * 2], BH[nt * 2 + 1]);
        }
    }

    const int m0 = bm * BM + warp_m * 64 + (lane >> 2);
    const int n0 = bn * BN + warp_n * 32 + (lane & 3) * 2;
    #pragma unroll
    for (int mt = 0; mt < 4; mt++)
        #pragma unroll
        for (int nt = 0; nt < 4; nt++) {
            __half* p0 = C + (size_t)(m0 + mt * 16) * HID + n0 + nt * 8;
            __half* p1 = C + (size_t)(m0 + mt * 16 + 8) * HID + n0 + nt * 8;
            *(__half2*)p0 = __floats2half2_rn(acc[mt][nt][0], acc[mt][nt][1]);
            *(__half2*)p1 = __floats2half2_rn(acc[mt][nt][2], acc[mt][nt][3]);
        }
}

// ---------------- candidate select: smem-key, plain-atomic windowed radix ----------------
// Identical Kcut semantics to R10; ballots/match_any removed (pass rate is so low
// post-windowing that plain predicated smem atomics beat aggregation overhead).
__device__ __forceinline__ void scan_hist(const unsigned* hist, int T, int lane,
                                          int* sh_cross, int* sh_rem, int* sh_total)
{
    unsigned h8[8];
    int s = 0;
    #pragma unroll
    for (int j = 0; j < 8; j++) { h8[j] = hist[lane * 8 + j]; s += (int)h8[j]; }
    int t = s;
    #pragma unroll
    for (int o = 1; o < 32; o <<= 1) {
        int v = __shfl_down_sync(0xffffffffu, t, o);
        if (lane + o < 32) t += v;
    }
    int above = __shfl_down_sync(0xffffffffu, t, 1);
    if (lane == 31) above = 0;
    const int total = __shfl_sync(0xffffffffu, t, 0);
    int cum = above;
    #pragma unroll
    for (int j = 7; j >= 0; j--) {
        if (cum < T && cum + (int)h8[j] >= T) {
            *sh_cross = lane * 8 + j;
            *sh_rem = T - cum;
        }
        cum += (int)h8[j];
    }
    if (lane == 0) *sh_total = total;
}

__global__ void __launch_bounds__(256) select_kernel(
    const __half* __restrict__ S, int* __restrict__ cand, int* __restrict__ ccnt,
    const int* __restrict__ topk_ptr)
{
    uint32_t* kp = (uint32_t*)dynsmem;      // 8192 packed key16 pairs (32 KB)
    __shared__ unsigned hist[256];
    __shared__ unsigned wmax[8];
    __shared__ int sh_cross, sh_rem, sh_total, sh_cnt, sh_lb;

    const int n = blockIdx.x, tid = threadIdx.x;
    const int wid = tid >> 5, lane = tid & 31;
    const int T = *topk_ptr + 8;

    // load 64 halves/thread -> packed key16 pairs into smem; track max en route
    const uint4* g4 = (const uint4*)(S + (size_t)n * HID);
    uint32_t mymax = 0;
    #pragma unroll
    for (int i = 0; i < 8; i++) {
        const int w4 = tid + i * 256;
        uint4 v = g4[w4];
        uint32_t wsv[4] = {v.x, v.y, v.z, v.w};
        #pragma unroll
        for (int c = 0; c < 4; c++) {
            uint32_t w = wsv[c];
            uint32_t m = (w >> 15) & 0x00010001u;
            uint32_t key = w ^ ((m * 0xFFFFu) | 0x80008000u);
            kp[w4 * 4 + c] = key;
            mymax = max(mymax, max(key & 0xFFFF0000u, key << 16));
        }
    }
    mymax >>= 16;
    #pragma unroll
    for (int o = 16; o > 0; o >>= 1)
        mymax = max(mymax, __shfl_xor_sync(0xffffffffu, mymax, o));
    if (lane == 0) wmax[wid] = mymax;
    if (tid == 0) { sh_cnt = 0; sh_cross = 255; sh_rem = T; sh_lb = 255; sh_total = 0; }
    hist[tid] = 0u;
    __syncthreads();
    uint32_t maxkey = 0;
    #pragma unroll
    for (int j = 0; j < 8; j++) maxkey = max(maxkey, wmax[j]);
    int floorA = (int)(maxkey >> 8) - 4;   // one octave below row max
    if (floorA < 0) floorA = 0;

    // phase A: histogram high bytes in [floorA, 256) — plain predicated atomics
    #pragma unroll
    for (int i = 0; i < 32; i++) {
        const uint32_t key = kp[tid + i * 256];
        const int hb0 = (int)((key >> 8) & 0xFFu);
        const int hb1 = (int)(key >> 24);
        if (hb0 >= floorA) atomicAdd(&hist[hb0], 1u);
        if (hb1 >= floorA) atomicAdd(&hist[hb1], 1u);
    }
    __syncthreads();
    if (wid == 0) scan_hist(hist, T, lane, &sh_cross, &sh_rem, &sh_total);
    __syncthreads();

    // phase B (at most once): cover remaining bins [0, floorA); full coverage after.
    if (sh_total < T && floorA > 0) {
        #pragma unroll
        for (int i = 0; i < 32; i++) {
            const uint32_t key = kp[tid + i * 256];
            const int hb0 = (int)((key >> 8) & 0xFFu);
            const int hb1 = (int)(key >> 24);
            if (hb0 < floorA) atomicAdd(&hist[hb0], 1u);
            if (hb1 < floorA) atomicAdd(&hist[hb1], 1u);
        }
        __syncthreads();
        if (wid == 0) scan_hist(hist, T, lane, &sh_cross, &sh_rem, &sh_total);
        __syncthreads();
    }
    const int cross = sh_cross, rem = sh_rem;
    __syncthreads();
    hist[tid] = 0u;
    __syncthreads();

    // low-byte histogram within crossing bin — plain predicated atomics
    #pragma unroll
    for (int i = 0; i < 32; i++) {
        const uint32_t key = kp[tid + i * 256];
        const unsigned k0 = key & 0xFFFFu;
        const unsigned k1 = key >> 16;
        if ((int)(k0 >> 8) == cross) atomicAdd(&hist[k0 & 0xFFu], 1u);
        if ((int)(k1 >> 8) == cross) atomicAdd(&hist[k1 & 0xFFu], 1u);
    }
    __syncthreads();
    if (wid == 0) scan_hist(hist, rem, lane, &sh_lb, &sh_rem, &sh_total);
    __syncthreads();
    const unsigned Kcut = ((unsigned)cross << 8) | (unsigned)sh_lb;

    // gather candidates — plain atomic append (order nondeterministic; refine is
    // order-independent: ranks by value, compacts by index)
    #pragma unroll
    for (int i = 0; i < 32; i++) {
        const int w = tid + i * 256;        // word index; element = w*2 + h
        const uint32_t key = kp[w];
        const unsigned k0 = key & 0xFFFFu;
        const unsigned k1 = key >> 16;
        if (k0 >= Kcut) {
            int p = atomicAdd(&sh_cnt, 1);
            if (p < 64) cand[n * 64 + p] = w * 2;
        }
        if (k1 >= Kcut) {
            int p = atomicAdd(&sh_cnt, 1);
            if (p < 64) cand[n * 64 + p] = w * 2 + 1;
        }
    }
    __syncthreads();
    if (tid == 0) ccnt[n] = min(sh_cnt, 64);
}

// ---------------- refine: EXACT round-1 arithmetic on candidates ----------------
__global__ void __launch_bounds__(256) refine_kernel(
    const float* __restrict__ Eraw, const float* __restrict__ Wraw,
    const float* __restrict__ invE, const float* __restrict__ invW,
    const int* __restrict__ cand, const int* __restrict__ ccnt,
    float* __restrict__ latent, int* __restrict__ acnt,
    int* __restrict__ aidx, float* __restrict__ aval,
    const int* __restrict__ topk_ptr)
{
    float* es = (float*)dynsmem;          // 768 floats (raw E row)
    float* ws = es + 768;                 // 16 rows x 772 floats (raw W rows)
    __shared__ float simc[64];
    __shared__ int   ridx[64];
    __shared__ int   skeep[64];
    __shared__ float sh_thres;

    const int n = blockIdx.x, tid = threadIdx.x;
    const int cnt = min(ccnt[n], 64);
    const int K = *topk_ptr;
    const float ie = invE[n];

    if (tid == 0) sh_thres = -1e30f;
    if (tid < 192) ((float4*)es)[tid] = ((const float4*)(Eraw + (size_t)n * DIM))[tid];
    __syncthreads();

    for (int base = 0; base < cnt; base += 16) {
        const int nthis = min(16, cnt - base);
        const int r = tid >> 4, part = tid & 15;
        if (r < nthis) {
            const float4* wr = (const float4*)(Wraw + (size_t)cand[n * 64 + base + r] * DIM);
            float4* wd = (float4*)(ws + r * 772);
            #pragma unroll
            for (int j = 0; j < 12; j++) wd[part + j * 16] = wr[part + j * 16];
        }
        __syncthreads();
        if (tid < nthis) {
            const int id = cand[n * 64 + base + tid];
            const float* wrow = ws + tid * 772;
            float s = 0.f;
            for (int k = 0; k < DIM; k++) s = fmaf(es[k], wrow[k], s);
            float cosv = s * ie * invW[id];
            float t = fmaxf(2.0f - 2.0f * cosv, 0.0f);
            simc[base + tid] = 2.0f - sqrtf(t);
            ridx[base + tid] = id;
        }
        __syncthreads();
    }

    if (tid < cnt) {
        float x = simc[tid];
        int id = ridx[tid];
        int r = 0;
        for (int j = 0; j < cnt; j++)
            r += (simc[j] > x) || (simc[j] == x && ridx[j] < id);
        if (r == K) sh_thres = x;
    }
    __syncthreads();
    const float thres = sh_thres;
    if (tid < 64) skeep[tid] = (tid < cnt) ? (simc[tid] > thres ? 1 : 0) : 0;
    __syncthreads();
    if (tid < cnt && skeep[tid]) {
        float sim = simc[tid];
        latent[(size_t)n * HID + ridx[tid]] = sim;
        int pos = 0;
        for (int j = 0; j < cnt; j++)
            pos += (skeep[j] && ridx[j] < ridx[tid]) ? 1 : 0;
        aidx[n * 64 + pos] = ridx[tid];
        aval[n * 64 + pos] = sim;
    }
    if (tid == 0) {
        int tot = 0;
        for (int j = 0; j < cnt; j++) tot += skeep[j];
        acnt[n] = tot;
    }
}

// ---------------- transpose W [DIM][HID] -> WT [HID][DIM] ----------------
__global__ void transpose_kernel(const float* __restrict__ Win, float* __restrict__ Wout)
{
    __shared__ float t[32][33];
    const int h0 = blockIdx.x * 32, d0 = blockIdx.y * 32;
    const int x = threadIdx.x, y = threadIdx.y;
    #pragma unroll
    for (int i = y; i < 32; i += 8)
        t[i][x] = Win[(size_t)(d0 + i) * HID + h0 + x];
    __syncthreads();
    #pragma unroll
    for (int i = y; i < 32; i += 8)
        Wout[(size_t)(h0 + i) * DIM + d0 + x] = t[x][i];
}

// ---------------- sparse reconstruction ----------------
__global__ void __launch_bounds__(256) recon_kernel(
    const float* __restrict__ WT, const float* __restrict__ bias,
    float* __restrict__ R, const int* __restrict__ acnt,
    const int* __restrict__ aidx, const float* __restrict__ aval)
{
    const int n = blockIdx.x, tid = threadIdx.x;
    __shared__ int   sidx[64];
    __shared__ float sval[64];
    int c = acnt[n];
    if (c > 64) c = 64;
    if (tid < 64) {
        sidx[tid] = aidx[n * 64 + tid];
        sval[tid] = aval[n * 64 + tid];
    }
    __syncthreads();
    float a0 = bias[tid], a1 = bias[tid + 256], a2 = bias[tid + 512];
    for (int j = 0; j < c; j++) {
        const float* w = WT + (size_t)sidx[j] * DIM;
        const float v = sval[j];
        a0 = fmaf(v, w[tid],       a0);
        a1 = fmaf(v, w[tid + 256], a1);
        a2 = fmaf(v, w[tid + 512], a2);
    }
    float* r = R + (size_t)n * DIM;
    r[tid] = a0; r[tid + 256] = a1; r[tid + 512] = a2;
}

// ---------------- host ----------------
extern "C" void kernel_launch(void* const* d_in, const int* in_sizes, int n_in,
                              void* d_out, int out_size)
{
    const float* Ev  = (const float*)d_in[0];
    const float* Et  = (const float*)d_in[1];
    const float* Enc = (const float*)d_in[2];
    const float* Wv  = (const float*)d_in[3];
    const float* bv  = (const float*)d_in[4];
    const float* Wt  = (const float*)d_in[5];
    const float* bt  = (const float*)d_in[6];
    const int*   tk  = (const int*)d_in[7];

    float* out = (float*)d_out;
    float* recon_v  = out;
    float* recon_t  = out + (size_t)N_ROWS * DIM;
    float* latent_v = out + (size_t)2 * N_ROWS * DIM;
    float* latent_t = latent_v + (size_t)N_ROWS * HID;

    __half *p_cosh, *p_Enh, *p_Wnh;
    float *p_WT, *p_invE, *p_invW, *p_aval;
    int *p_cand, *p_ccnt, *p_aidx, *p_acnt;
    cudaGetSymbolAddress((void**)&p_cosh, g_cosh);
    cudaGetSymbolAddress((void**)&p_WT,   g_WT);
    cudaGetSymbolAddress((void**)&p_invE, g_invE);
    cudaGetSymbolAddress((void**)&p_invW, g_invW);
    cudaGetSymbolAddress((void**)&p_Enh,  g_Enh);
    cudaGetSymbolAddress((void**)&p_Wnh,  g_Wnh);
    cudaGetSymbolAddress((void**)&p_cand, g_cand);
    cudaGetSymbolAddress((void**)&p_ccnt, g_ccnt);
    cudaGetSymbolAddress((void**)&p_aidx, g_aidx);
    cudaGetSymbolAddress((void**)&p_aval, g_aval);
    cudaGetSymbolAddress((void**)&p_acnt, g_acnt);

    cudaFuncSetAttribute(cos_gemm_kernel, cudaFuncAttributeMaxDynamicSharedMemorySize, SMEM_GEMM);
    cudaFuncSetAttribute(select_kernel,   cudaFuncAttributeMaxDynamicSharedMemorySize, SELECT_SMEM);
    cudaFuncSetAttribute(refine_kernel,   cudaFuncAttributeMaxDynamicSharedMemorySize, REFINE_SMEM);

    const dim3 tb(32, 8);
    const dim3 ggrid(HID / BN, N_ROWS / BM);   // (128, 32)

    normhalf_kernel<<<HID / 8, tb>>>(Enc, p_invW, p_Wnh, HID);

    // ---- vision ----
    normhalf_kernel<<<N_ROWS / 8, tb>>>(Ev, p_invE, p_Enh, N_ROWS);
    cos_gemm_kernel<<<ggrid, 256, SMEM_GEMM>>>(p_Enh, p_Wnh, p_cosh);
    select_kernel<<<N_ROWS, 256, SELECT_SMEM>>>(p_cosh, p_cand, p_ccnt, tk);
    cudaMemsetAsync(latent_v, 0, (size_t)2 * N_ROWS * HID * sizeof(float));
    refine_kernel<<<N_ROWS, 256, REFINE_SMEM>>>(Ev, Enc, p_invE, p_invW, p_cand, p_ccnt,
                                                latent_v, p_acnt, p_aidx, p_aval, tk);
    transpose_kernel<<<dim3(HID / 32, DIM / 32), tb>>>(Wv, p_WT);
    recon_kernel<<<N_ROWS, 256>>>(p_WT, bv, recon_v, p_acnt, p_aidx, p_aval);

    // ---- text ----
    normhalf_kernel<<<N_ROWS / 8, tb>>>(Et, p_invE, p_Enh, N_ROWS);
    cos_gemm_kernel<<<ggrid, 256, SMEM_GEMM>>>(p_Enh, p_Wnh, p_cosh);
    select_kernel<<<N_ROWS, 256, SELECT_SMEM>>>(p_cosh, p_cand, p_ccnt, tk);
    refine_kernel<<<N_ROWS, 256, REFINE_SMEM>>>(Et, Enc, p_invE, p_invW, p_cand, p_ccnt,
                                                latent_t, p_acnt, p_aidx, p_aval, tk);
    transpose_kernel<<<dim3(HID / 32, DIM / 32), tb>>>(Wt, p_WT);
    recon_kernel<<<N_ROWS, 256>>>(p_WT, bt, recon_t, p_acnt, p_aidx, p_aval);
}

// round 15
// speedup vs baseline: 1.1516x; 1.0379x over previous
#include <cuda_runtime.h>
#include <cuda_fp16.h>
#include <cstdint>

#define N_ROWS 4096
#define DIM    768
#define HID    16384

// GEMM tiling (BM=128 x BN=128, 256 threads, 2 CTAs/SM)
#define BM 128
#define BN 128
#define BK 32
#define NKT (DIM / BK)          // 24
#define PITCH_H 40              // halves per smem row (80B, LDSM conflict-free)
#define ARR_BYTES (128 * PITCH_H * 2)   // 10240 B per array (128 rows x BK)
#define STAGE_BYTES (2 * ARR_BYTES)     // A | B = 20480
#define SMEM_GEMM (3 * STAGE_BYTES)     // 61440 (3-stage)

#define REFINE_SMEM (3072 + 16 * 772 * 4)   // es[768] + ws[16][772]
#define SELECT_SMEM 32768                   // 8192 packed key words

// ---------------- scratch (static device globals; no allocation) ----------------
// per-modality double buffers (vision = [0], text = [1]) for stream overlap
__device__ __half g_cosh_v[(size_t)N_ROWS * HID];
__device__ __half g_cosh_t[(size_t)N_ROWS * HID];
__device__ float  g_WT_v[(size_t)HID * DIM];
__device__ float  g_WT_t[(size_t)HID * DIM];
__device__ float  g_invE_v[N_ROWS];
__device__ float  g_invE_t[N_ROWS];
__device__ float  g_invW[HID];
__device__ __half g_Enh_v[(size_t)N_ROWS * DIM];
__device__ __half g_Enh_t[(size_t)N_ROWS * DIM];
__device__ __half g_Wnh[(size_t)HID * DIM];
__device__ int    g_cand_v[N_ROWS * 64];
__device__ int    g_cand_t[N_ROWS * 64];
__device__ int    g_ccnt_v[N_ROWS];
__device__ int    g_ccnt_t[N_ROWS];
__device__ int    g_aidx_v[N_ROWS * 64];
__device__ int    g_aidx_t[N_ROWS * 64];
__device__ float  g_aval_v[N_ROWS * 64];
__device__ float  g_aval_t[N_ROWS * 64];
__device__ int    g_acnt_v[N_ROWS];
__device__ int    g_acnt_t[N_ROWS];

extern __shared__ __align__(1024) char dynsmem[];

// ---------------- PTX helpers (base-target ISA only) ----------------
__device__ __forceinline__ uint32_t smem_u32(const void* p) {
    uint32_t a;
    asm("{ .reg .u64 t; cvta.to.shared.u64 t, %1; cvt.u32.u64 %0, t; }" : "=r"(a) : "l"(p));
    return a;
}
__device__ __forceinline__ void cp16(uint32_t dst, const void* src) {
    asm volatile("cp.async.cg.shared.global [%0], [%1], 16;" :: "r"(dst), "l"(src));
}
__device__ __forceinline__ void cp_commit() { asm volatile("cp.async.commit_group;"); }
__device__ __forceinline__ void cp_wait1()  { asm volatile("cp.async.wait_group 1;"); }
__device__ __forceinline__ void ldsm_x4(uint32_t* r, uint32_t addr) {
    asm volatile("ldmatrix.sync.aligned.m8n8.x4.shared.b16 {%0,%1,%2,%3}, [%4];"
                 : "=r"(r[0]), "=r"(r[1]), "=r"(r[2]), "=r"(r[3]) : "r"(addr));
}
__device__ __forceinline__ void mma16816(float* c, const uint32_t* a, uint32_t b0, uint32_t b1) {
    asm volatile(
        "mma.sync.aligned.m16n8k16.row.col.f32.f16.f16.f32 "
        "{%0,%1,%2,%3}, {%4,%5,%6,%7}, {%8,%9}, {%0,%1,%2,%3};"
        : "+f"(c[0]), "+f"(c[1]), "+f"(c[2]), "+f"(c[3])
        : "r"(a[0]), "r"(a[1]), "r"(a[2]), "r"(a[3]), "r"(b0), "r"(b1));
}

// ---------------- fused: EXACT round-1 inverse norm + normalized f16 copy ----------------
__global__ void normhalf_kernel(const float* __restrict__ X, float* __restrict__ inv,
                                __half* __restrict__ Xh, int rows)
{
    int row = blockIdx.x * 8 + threadIdx.y;
    if (row >= rows) return;
    const float* p = X + (size_t)row * DIM;
    float v[24];
    float s = 0.f;
    #pragma unroll
    for (int q = 0; q < 24; q++) {
        v[q] = p[threadIdx.x + q * 32];
        s = fmaf(v[q], v[q], s);
    }
    #pragma unroll
    for (int o = 16; o > 0; o >>= 1) s += __shfl_xor_sync(0xffffffffu, s, o);
    float iv = 1.0f / fmaxf(sqrtf(s), 1e-12f);
    if (threadIdx.x == 0) inv[row] = iv;
    __half* hp = Xh + (size_t)row * DIM;
    #pragma unroll
    for (int q = 0; q < 24; q++)
        hp[threadIdx.x + q * 32] = __float2half_rn(v[q] * iv);
}

// ---------------- HMMA f16 GEMM: cos_h = En . WnT ----------------
__global__ void __launch_bounds__(256, 2) cos_gemm_kernel(
    const __half* __restrict__ Ah, const __half* __restrict__ Bh,
    __half* __restrict__ C)
{
    char* smem = dynsmem;
    const uint32_t sb = smem_u32(smem);
    const int tid = threadIdx.x, wid = tid >> 5, lane = tid & 31;
    const int warp_m = wid >> 2, warp_n = wid & 3;   // 2 x 4 warps
    const int bn = blockIdx.x, bm = blockIdx.y;

    const __half* gsrc[2] = {Ah + (size_t)bm * BM * DIM, Bh + (size_t)bn * BN * DIM};

    const int r0c = tid >> 2, c0c = tid & 3;
    const int r1c = (tid + 256) >> 2;

    const int a_tile = lane >> 3, a_r = lane & 7;
    const uint32_t a_off = (uint32_t)((warp_m * 64 + (a_tile & 1) * 8 + a_r) * (PITCH_H * 2)
                                      + ((a_tile >> 1) * 8) * 2);
    const uint32_t b_off = (uint32_t)((warp_n * 32 + (a_tile >> 1) * 8 + a_r) * (PITCH_H * 2)
                                      + ((a_tile & 1) * 8) * 2);

    float acc[4][4][4];
    #pragma unroll
    for (int i = 0; i < 4; i++)
        #pragma unroll
        for (int j = 0; j < 4; j++)
            #pragma unroll
            for (int q = 0; q < 4; q++) acc[i][j][q] = 0.f;

    auto issue = [&](int s) {
        if (s < NKT) {
            const int kb = s * BK;
            const uint32_t stg = sb + (uint32_t)(s % 3) * STAGE_BYTES;
            #pragma unroll
            for (int arr = 0; arr < 2; arr++) {
                const uint32_t sa = stg + arr * ARR_BYTES;
                cp16(sa + r0c * (PITCH_H * 2) + c0c * 16, gsrc[arr] + (size_t)r0c * DIM + kb + c0c * 8);
                cp16(sa + r1c * (PITCH_H * 2) + c0c * 16, gsrc[arr] + (size_t)r1c * DIM + kb + c0c * 8);
            }
        }
        cp_commit();
    };

    issue(0);
    issue(1);

    for (int kt = 0; kt < NKT; ++kt) {
        cp_wait1();
        __syncthreads();
        issue(kt + 2);
        const uint32_t stg = sb + (uint32_t)(kt % 3) * STAGE_BYTES;
        #pragma unroll
        for (int ks = 0; ks < 2; ++ks) {
            const uint32_t kadd = (uint32_t)(ks * 16 * 2);
            uint32_t AH[16], BH[8];
            #pragma unroll
            for (int mt = 0; mt < 4; mt++)
                ldsm_x4(&AH[mt * 4], stg + a_off + mt * 16 * (PITCH_H * 2) + kadd);
            #pragma unroll
            for (int np = 0; np < 2; np++)
                ldsm_x4(&BH[np * 4], stg + ARR_BYTES + b_off + np * 16 * (PITCH_H * 2) + kadd);
            #pragma unroll
            for (int mt = 0; mt < 4; mt++)
                #pragma unroll
                for (int nt = 0; nt < 4; nt++)
                    mma16816(acc[mt][nt], &AH[mt * 4], BH[nt * 2], BH[nt * 2 + 1]);
        }
    }

    const int m0 = bm * BM + warp_m * 64 + (lane >> 2);
    const int n0 = bn * BN + warp_n * 32 + (lane & 3) * 2;
    #pragma unroll
    for (int mt = 0; mt < 4; mt++)
        #pragma unroll
        for (int nt = 0; nt < 4; nt++) {
            __half* p0 = C + (size_t)(m0 + mt * 16) * HID + n0 + nt * 8;
            __half* p1 = C + (size_t)(m0 + mt * 16 + 8) * HID + n0 + nt * 8;
            *(__half2*)p0 = __floats2half2_rn(acc[mt][nt][0], acc[mt][nt][1]);
            *(__half2*)p1 = __floats2half2_rn(acc[mt][nt][2], acc[mt][nt][3]);
        }
}

// ---------------- candidate select: smem-key, plain-atomic windowed radix ----------------
__device__ __forceinline__ void scan_hist(const unsigned* hist, int T, int lane,
                                          int* sh_cross, int* sh_rem, int* sh_total)
{
    unsigned h8[8];
    int s = 0;
    #pragma unroll
    for (int j = 0; j < 8; j++) { h8[j] = hist[lane * 8 + j]; s += (int)h8[j]; }
    int t = s;
    #pragma unroll
    for (int o = 1; o < 32; o <<= 1) {
        int v = __shfl_down_sync(0xffffffffu, t, o);
        if (lane + o < 32) t += v;
    }
    int above = __shfl_down_sync(0xffffffffu, t, 1);
    if (lane == 31) above = 0;
    const int total = __shfl_sync(0xffffffffu, t, 0);
    int cum = above;
    #pragma unroll
    for (int j = 7; j >= 0; j--) {
        if (cum < T && cum + (int)h8[j] >= T) {
            *sh_cross = lane * 8 + j;
            *sh_rem = T - cum;
        }
        cum += (int)h8[j];
    }
    if (lane == 0) *sh_total = total;
}

__global__ void __launch_bounds__(256) select_kernel(
    const __half* __restrict__ S, int* __restrict__ cand, int* __restrict__ ccnt,
    const int* __restrict__ topk_ptr)
{
    uint32_t* kp = (uint32_t*)dynsmem;      // 8192 packed key16 pairs (32 KB)
    __shared__ unsigned hist[256];
    __shared__ unsigned wmax[8];
    __shared__ int sh_cross, sh_rem, sh_total, sh_cnt, sh_lb;

    const int n = blockIdx.x, tid = threadIdx.x;
    const int wid = tid >> 5, lane = tid & 31;
    const int T = *topk_ptr + 8;

    const uint4* g4 = (const uint4*)(S + (size_t)n * HID);
    uint32_t mymax = 0;
    #pragma unroll
    for (int i = 0; i < 8; i++) {
        const int w4 = tid + i * 256;
        uint4 v = g4[w4];
        uint32_t wsv[4] = {v.x, v.y, v.z, v.w};
        #pragma unroll
        for (int c = 0; c < 4; c++) {
            uint32_t w = wsv[c];
            uint32_t m = (w >> 15) & 0x00010001u;
            uint32_t key = w ^ ((m * 0xFFFFu) | 0x80008000u);
            kp[w4 * 4 + c] = key;
            mymax = max(mymax, max(key & 0xFFFF0000u, key << 16));
        }
    }
    mymax >>= 16;
    #pragma unroll
    for (int o = 16; o > 0; o >>= 1)
        mymax = max(mymax, __shfl_xor_sync(0xffffffffu, mymax, o));
    if (lane == 0) wmax[wid] = mymax;
    if (tid == 0) { sh_cnt = 0; sh_cross = 255; sh_rem = T; sh_lb = 255; sh_total = 0; }
    hist[tid] = 0u;
    __syncthreads();
    uint32_t maxkey = 0;
    #pragma unroll
    for (int j = 0; j < 8; j++) maxkey = max(maxkey, wmax[j]);
    int floorA = (int)(maxkey >> 8) - 4;
    if (floorA < 0) floorA = 0;

    // phase A
    #pragma unroll
    for (int i = 0; i < 32; i++) {
        const uint32_t key = kp[tid + i * 256];
        const int hb0 = (int)((key >> 8) & 0xFFu);
        const int hb1 = (int)(key >> 24);
        if (hb0 >= floorA) atomicAdd(&hist[hb0], 1u);
        if (hb1 >= floorA) atomicAdd(&hist[hb1], 1u);
    }
    __syncthreads();
    if (wid == 0) scan_hist(hist, T, lane, &sh_cross, &sh_rem, &sh_total);
    __syncthreads();

    // phase B (at most once)
    if (sh_total < T && floorA > 0) {
        #pragma unroll
        for (int i = 0; i < 32; i++) {
            const uint32_t key = kp[tid + i * 256];
            const int hb0 = (int)((key >> 8) & 0xFFu);
            const int hb1 = (int)(key >> 24);
            if (hb0 < floorA) atomicAdd(&hist[hb0], 1u);
            if (hb1 < floorA) atomicAdd(&hist[hb1], 1u);
        }
        __syncthreads();
        if (wid == 0) scan_hist(hist, T, lane, &sh_cross, &sh_rem, &sh_total);
        __syncthreads();
    }
    const int cross = sh_cross, rem = sh_rem;
    __syncthreads();
    hist[tid] = 0u;
    __syncthreads();

    // low-byte histogram within crossing bin
    #pragma unroll
    for (int i = 0; i < 32; i++) {
        const uint32_t key = kp[tid + i * 256];
        const unsigned k0 = key & 0xFFFFu;
        const unsigned k1 = key >> 16;
        if ((int)(k0 >> 8) == cross) atomicAdd(&hist[k0 & 0xFFu], 1u);
        if ((int)(k1 >> 8) == cross) atomicAdd(&hist[k1 & 0xFFu], 1u);
    }
    __syncthreads();
    if (wid == 0) scan_hist(hist, rem, lane, &sh_lb, &sh_rem, &sh_total);
    __syncthreads();
    const unsigned Kcut = ((unsigned)cross << 8) | (unsigned)sh_lb;

    // gather candidates
    #pragma unroll
    for (int i = 0; i < 32; i++) {
        const int w = tid + i * 256;
        const uint32_t key = kp[w];
        const unsigned k0 = key & 0xFFFFu;
        const unsigned k1 = key >> 16;
        if (k0 >= Kcut) {
            int p = atomicAdd(&sh_cnt, 1);
            if (p < 64) cand[n * 64 + p] = w * 2;
        }
        if (k1 >= Kcut) {
            int p = atomicAdd(&sh_cnt, 1);
            if (p < 64) cand[n * 64 + p] = w * 2 + 1;
        }
    }
    __syncthreads();
    if (tid == 0) ccnt[n] = min(sh_cnt, 64);
}

// ---------------- refine: EXACT round-1 arithmetic on candidates ----------------
__global__ void __launch_bounds__(256) refine_kernel(
    const float* __restrict__ Eraw, const float* __restrict__ Wraw,
    const float* __restrict__ invE, const float* __restrict__ invW,
    const int* __restrict__ cand, const int* __restrict__ ccnt,
    float* __restrict__ latent, int* __restrict__ acnt,
    int* __restrict__ aidx, float* __restrict__ aval,
    const int* __restrict__ topk_ptr)
{
    float* es = (float*)dynsmem;
    float* ws = es + 768;
    __shared__ float simc[64];
    __shared__ int   ridx[64];
    __shared__ int   skeep[64];
    __shared__ float sh_thres;

    const int n = blockIdx.x, tid = threadIdx.x;
    const int cnt = min(ccnt[n], 64);
    const int K = *topk_ptr;
    const float ie = invE[n];

    if (tid == 0) sh_thres = -1e30f;
    if (tid < 192) ((float4*)es)[tid] = ((const float4*)(Eraw + (size_t)n * DIM))[tid];
    __syncthreads();

    for (int base = 0; base < cnt; base += 16) {
        const int nthis = min(16, cnt - base);
        const int r = tid >> 4, part = tid & 15;
        if (r < nthis) {
            const float4* wr = (const float4*)(Wraw + (size_t)cand[n * 64 + base + r] * DIM);
            float4* wd = (float4*)(ws + r * 772);
            #pragma unroll
            for (int j = 0; j < 12; j++) wd[part + j * 16] = wr[part + j * 16];
        }
        __syncthreads();
        if (tid < nthis) {
            const int id = cand[n * 64 + base + tid];
            const float* wrow = ws + tid * 772;
            float s = 0.f;
            for (int k = 0; k < DIM; k++) s = fmaf(es[k], wrow[k], s);
            float cosv = s * ie * invW[id];
            float t = fmaxf(2.0f - 2.0f * cosv, 0.0f);
            simc[base + tid] = 2.0f - sqrtf(t);
            ridx[base + tid] = id;
        }
        __syncthreads();
    }

    if (tid < cnt) {
        float x = simc[tid];
        int id = ridx[tid];
        int r = 0;
        for (int j = 0; j < cnt; j++)
            r += (simc[j] > x) || (simc[j] == x && ridx[j] < id);
        if (r == K) sh_thres = x;
    }
    __syncthreads();
    const float thres = sh_thres;
    if (tid < 64) skeep[tid] = (tid < cnt) ? (simc[tid] > thres ? 1 : 0) : 0;
    __syncthreads();
    if (tid < cnt && skeep[tid]) {
        float sim = simc[tid];
        latent[(size_t)n * HID + ridx[tid]] = sim;
        int pos = 0;
        for (int j = 0; j < cnt; j++)
            pos += (skeep[j] && ridx[j] < ridx[tid]) ? 1 : 0;
        aidx[n * 64 + pos] = ridx[tid];
        aval[n * 64 + pos] = sim;
    }
    if (tid == 0) {
        int tot = 0;
        for (int j = 0; j < cnt; j++) tot += skeep[j];
        acnt[n] = tot;
    }
}

// ---------------- transpose W [DIM][HID] -> WT [HID][DIM] ----------------
__global__ void transpose_kernel(const float* __restrict__ Win, float* __restrict__ Wout)
{
    __shared__ float t[32][33];
    const int h0 = blockIdx.x * 32, d0 = blockIdx.y * 32;
    const int x = threadIdx.x, y = threadIdx.y;
    #pragma unroll
    for (int i = y; i < 32; i += 8)
        t[i][x] = Win[(size_t)(d0 + i) * HID + h0 + x];
    __syncthreads();
    #pragma unroll
    for (int i = y; i < 32; i += 8)
        Wout[(size_t)(h0 + i) * DIM + d0 + x] = t[x][i];
}

// ---------------- sparse reconstruction ----------------
__global__ void __launch_bounds__(256) recon_kernel(
    const float* __restrict__ WT, const float* __restrict__ bias,
    float* __restrict__ R, const int* __restrict__ acnt,
    const int* __restrict__ aidx, const float* __restrict__ aval)
{
    const int n = blockIdx.x, tid = threadIdx.x;
    __shared__ int   sidx[64];
    __shared__ float sval[64];
    int c = acnt[n];
    if (c > 64) c = 64;
    if (tid < 64) {
        sidx[tid] = aidx[n * 64 + tid];
        sval[tid] = aval[n * 64 + tid];
    }
    __syncthreads();
    float a0 = bias[tid], a1 = bias[tid + 256], a2 = bias[tid + 512];
    for (int j = 0; j < c; j++) {
        const float* w = WT + (size_t)sidx[j] * DIM;
        const float v = sval[j];
        a0 = fmaf(v, w[tid],       a0);
        a1 = fmaf(v, w[tid + 256], a1);
        a2 = fmaf(v, w[tid + 512], a2);
    }
    float* r = R + (size_t)n * DIM;
    r[tid] = a0; r[tid + 256] = a1; r[tid + 512] = a2;
}

// ---------------- host ----------------
extern "C" void kernel_launch(void* const* d_in, const int* in_sizes, int n_in,
                              void* d_out, int out_size)
{
    const float* Ev  = (const float*)d_in[0];
    const float* Et  = (const float*)d_in[1];
    const float* Enc = (const float*)d_in[2];
    const float* Wv  = (const float*)d_in[3];
    const float* bv  = (const float*)d_in[4];
    const float* Wt  = (const float*)d_in[5];
    const float* bt  = (const float*)d_in[6];
    const int*   tk  = (const int*)d_in[7];

    float* out = (float*)d_out;
    float* recon_v  = out;
    float* recon_t  = out + (size_t)N_ROWS * DIM;
    float* latent_v = out + (size_t)2 * N_ROWS * DIM;
    float* latent_t = latent_v + (size_t)N_ROWS * HID;

    __half *p_cosh_v, *p_cosh_t, *p_Enh_v, *p_Enh_t, *p_Wnh;
    float *p_WT_v, *p_WT_t, *p_invE_v, *p_invE_t, *p_invW, *p_aval_v, *p_aval_t;
    int *p_cand_v, *p_cand_t, *p_ccnt_v, *p_ccnt_t, *p_aidx_v, *p_aidx_t, *p_acnt_v, *p_acnt_t;
    cudaGetSymbolAddress((void**)&p_cosh_v, g_cosh_v);
    cudaGetSymbolAddress((void**)&p_cosh_t, g_cosh_t);
    cudaGetSymbolAddress((void**)&p_WT_v,   g_WT_v);
    cudaGetSymbolAddress((void**)&p_WT_t,   g_WT_t);
    cudaGetSymbolAddress((void**)&p_invE_v, g_invE_v);
    cudaGetSymbolAddress((void**)&p_invE_t, g_invE_t);
    cudaGetSymbolAddress((void**)&p_invW,   g_invW);
    cudaGetSymbolAddress((void**)&p_Enh_v,  g_Enh_v);
    cudaGetSymbolAddress((void**)&p_Enh_t,  g_Enh_t);
    cudaGetSymbolAddress((void**)&p_Wnh,    g_Wnh);
    cudaGetSymbolAddress((void**)&p_cand_v, g_cand_v);
    cudaGetSymbolAddress((void**)&p_cand_t, g_cand_t);
    cudaGetSymbolAddress((void**)&p_ccnt_v, g_ccnt_v);
    cudaGetSymbolAddress((void**)&p_ccnt_t, g_ccnt_t);
    cudaGetSymbolAddress((void**)&p_aidx_v, g_aidx_v);
    cudaGetSymbolAddress((void**)&p_aidx_t, g_aidx_t);
    cudaGetSymbolAddress((void**)&p_aval_v, g_aval_v);
    cudaGetSymbolAddress((void**)&p_aval_t, g_aval_t);
    cudaGetSymbolAddress((void**)&p_acnt_v, g_acnt_v);
    cudaGetSymbolAddress((void**)&p_acnt_t, g_acnt_t);

    cudaFuncSetAttribute(cos_gemm_kernel, cudaFuncAttributeMaxDynamicSharedMemorySize, SMEM_GEMM);
    cudaFuncSetAttribute(select_kernel,   cudaFuncAttributeMaxDynamicSharedMemorySize, SELECT_SMEM);
    cudaFuncSetAttribute(refine_kernel,   cudaFuncAttributeMaxDynamicSharedMemorySize, REFINE_SMEM);

    // one extra stream + fork/join events (created once; graph-capturable pattern)
    static cudaStream_t s1 = nullptr;
    static cudaEvent_t evFork = nullptr, evJoin = nullptr;
    if (s1 == nullptr) {
        cudaStreamCreateWithFlags(&s1, cudaStreamNonBlocking);
        cudaEventCreateWithFlags(&evFork, cudaEventDisableTiming);
        cudaEventCreateWithFlags(&evJoin, cudaEventDisableTiming);
    }
    cudaStream_t s0 = 0;   // harness-captured stream (legacy default)

    const dim3 tb(32, 8);
    const dim3 ggrid(HID / BN, N_ROWS / BM);

    // shared prologue on s0: encoder norm (used by both chains)
    normhalf_kernel<<<HID / 8, tb, 0, s0>>>(Enc, p_invW, p_Wnh, HID);
    cudaEventRecord(evFork, s0);

    // ---- vision chain on s0 ----
    normhalf_kernel<<<N_ROWS / 8, tb, 0, s0>>>(Ev, p_invE_v, p_Enh_v, N_ROWS);
    cudaMemsetAsync(latent_v, 0, (size_t)N_ROWS * HID * sizeof(float), s0);
    cos_gemm_kernel<<<ggrid, 256, SMEM_GEMM, s0>>>(p_Enh_v, p_Wnh, p_cosh_v);
    select_kernel<<<N_ROWS, 256, SELECT_SMEM, s0>>>(p_cosh_v, p_cand_v, p_ccnt_v, tk);
    refine_kernel<<<N_ROWS, 256, REFINE_SMEM, s0>>>(Ev, Enc, p_invE_v, p_invW, p_cand_v, p_ccnt_v,
                                                    latent_v, p_acnt_v, p_aidx_v, p_aval_v, tk);
    transpose_kernel<<<dim3(HID / 32, DIM / 32), tb, 0, s0>>>(Wv, p_WT_v);
    recon_kernel<<<N_ROWS, 256, 0, s0>>>(p_WT_v, bv, recon_v, p_acnt_v, p_aidx_v, p_aval_v);

    // ---- text chain on s1 (depends only on evFork for invW/Wnh) ----
    cudaStreamWaitEvent(s1, evFork, 0);
    normhalf_kernel<<<N_ROWS / 8, tb, 0, s1>>>(Et, p_invE_t, p_Enh_t, N_ROWS);
    cudaMemsetAsync(latent_t, 0, (size_t)N_ROWS * HID * sizeof(float), s1);
    cos_gemm_kernel<<<ggrid, 256, SMEM_GEMM, s1>>>(p_Enh_t, p_Wnh, p_cosh_t);
    select_kernel<<<N_ROWS, 256, SELECT_SMEM, s1>>>(p_cosh_t, p_cand_t, p_ccnt_t, tk);
    refine_kernel<<<N_ROWS, 256, REFINE_SMEM, s1>>>(Et, Enc, p_invE_t, p_invW, p_cand_t, p_ccnt_t,
                                                    latent_t, p_acnt_t, p_aidx_t, p_aval_t, tk);
    transpose_kernel<<<dim3(HID / 32, DIM / 32), tb, 0, s1>>>(Wt, p_WT_t);
    recon_kernel<<<N_ROWS, 256, 0, s1>>>(p_WT_t, bt, recon_t, p_acnt_t, p_aidx_t, p_aval_t);
    cudaEventRecord(evJoin, s1);

    // join
    cudaStreamWaitEvent(s0, evJoin, 0);
}